// round 1
// baseline (speedup 1.0000x reference)
#include <cuda_runtime.h>

// Problem constants
#define NN 50000
#define FF 64
#define HH 128

// ---------------- device scratch (static globals, no cudaMalloc) -------------
__device__ float g_deg[NN];
__device__ float g_dinv[NN];
__device__ float g_AX[(size_t)NN * FF];          // aggregated X  (N x 64)
__device__ float g_ZR[(size_t)NN * 256];         // Z in cols 0..127, R in 128..255
__device__ float g_reluh[(size_t)NN * HH];       // relu(h)
__device__ float g_Wcat[192 * 384];              // packed gate weights
__device__ float g_bcat[384];                    // packed gate biases

// ---------------- weight packing --------------------------------------------
// g_Wcat[k][j], k in [0,192), j in [0,384):
//   gate g = j/128 (0=z, 1=r, 2=h), jj = j%128
//   k <  64 : (W_g @ Lg_top)[k][jj]   (GCN weight folded into gate linear)
//   k >= 64 : Lg_w[128 + (k-64)][jj]  (bottom half: multiplies Hs (or Hs*R))
// g_bcat[j] = (b_g @ Lg_top)[jj] + Lg_b[jj]
__global__ void k_pack(const float* Wz, const float* bz,
                       const float* Wr, const float* br,
                       const float* Wh, const float* bh,
                       const float* Lz, const float* Lzb,
                       const float* Lr, const float* Lrb,
                       const float* Lh, const float* Lhb) {
    int idx = blockIdx.x * blockDim.x + threadIdx.x;
    const int total = 192 * 384;
    if (idx < total) {
        int k = idx / 384, j = idx % 384;
        int g = j >> 7;
        int jj = j & 127;
        const float* W = (g == 0) ? Wz : (g == 1) ? Wr : Wh;
        const float* L = (g == 0) ? Lz : (g == 1) ? Lr : Lh;
        float v;
        if (k < 64) {
            v = 0.f;
            #pragma unroll 8
            for (int t = 0; t < 128; t++) v += W[k * 128 + t] * L[t * 128 + jj];
        } else {
            v = L[(128 + (k - 64)) * 128 + jj];
        }
        g_Wcat[k * 384 + j] = v;
    } else if (idx < total + 384) {
        int j = idx - total;
        int g = j >> 7;
        int jj = j & 127;
        const float* bg = (g == 0) ? bz : (g == 1) ? br : bh;
        const float* L  = (g == 0) ? Lz : (g == 1) ? Lr : Lh;
        const float* Lb = (g == 0) ? Lzb : (g == 1) ? Lrb : Lhb;
        float v = Lb[jj];
        for (int t = 0; t < 128; t++) v += bg[t] * L[t * 128 + jj];
        g_bcat[j] = v;
    }
}

// ---------------- degree / normalization ------------------------------------
__global__ void k_initdeg() {
    int i = blockIdx.x * blockDim.x + threadIdx.x;
    if (i < NN) g_deg[i] = 1.0f;  // self-loop weight
}

__global__ void k_deg(const int* ei, const float* ew, int E) {
    int e = blockIdx.x * blockDim.x + threadIdx.x;
    if (e < E) atomicAdd(&g_deg[ei[E + e]], ew[e]);
}

__global__ void k_dinv() {
    int i = blockIdx.x * blockDim.x + threadIdx.x;
    if (i < NN) {
        float d = g_deg[i];
        g_dinv[i] = (d > 0.f) ? rsqrtf(d) : 0.f;
    }
}

// AX init = self-loop term: dinv[i]^2 * X[i,:]
__global__ void k_axinit(const float* __restrict__ X) {
    int tid = blockIdx.x * blockDim.x + threadIdx.x;
    if (tid >= NN * 16) return;
    int i = tid >> 4, q = tid & 15;
    float di = g_dinv[i];
    float s = di * di;
    float4 x = reinterpret_cast<const float4*>(X + (size_t)i * 64)[q];
    float4 v = make_float4(x.x * s, x.y * s, x.z * s, x.w * s);
    reinterpret_cast<float4*>(g_AX + (size_t)i * 64)[q] = v;
}

// Edge scatter: AX[dst] += dinv[src]*w*dinv[dst] * X[src]   (16 threads/edge)
__global__ void k_agg(const int* __restrict__ ei, const float* __restrict__ ew,
                      const float* __restrict__ X, int E) {
    int tid = blockIdx.x * blockDim.x + threadIdx.x;
    int e = tid >> 4;
    if (e >= E) return;
    int q = tid & 15;
    int s = ei[e];
    int d = ei[E + e];
    float norm = g_dinv[s] * ew[e] * g_dinv[d];
    float4 x = reinterpret_cast<const float4*>(X + (size_t)s * 64)[q];
    float* p = g_AX + (size_t)d * 64 + q * 4;
    asm volatile("red.global.add.v4.f32 [%0], {%1, %2, %3, %4};"
                 :: "l"(p), "f"(x.x * norm), "f"(x.y * norm),
                    "f"(x.z * norm), "f"(x.w * norm)
                 : "memory");
}

// ---------------- fused tiled SGEMM -----------------------------------------
// C[M x NC] = [A1 (M x K1) | A2 (M x K2) (optionally * R)] @ B(+colOff) + bias
// mode 0: sigmoid -> out0 (= g_ZR, stride NC=256)
// mode 1: tanh, GRU update -> out0 = h (stride 128), out1 = relu(h)
// mode 2: plain            -> out0 = y (stride 64)
#define BM 64
#define BN 64
#define BK 16
// 256 threads, each computes a 4x4 micro-tile

__global__ void __launch_bounds__(256)
gemm_kernel(const float* __restrict__ A1, int K1,
            const float* __restrict__ A2, int K2,
            const float* __restrict__ Rbuf,   // if non-null, A2 *= R (in g_ZR cols 128..255)
            const float* __restrict__ B, int ldb, int colOff,
            const float* __restrict__ bias,
            int NC, int mode,
            const float* __restrict__ Zbuf,   // mode 1: Z (g_ZR cols 0..127)
            const float* __restrict__ Hs,     // mode 1
            float* __restrict__ out0,
            float* __restrict__ out1) {
    __shared__ float As[BM][BK + 1];
    __shared__ float Bs[BK][BN];

    const int t = threadIdx.x;
    const int ty = t >> 4;       // 0..15 (row group)
    const int tx = t & 15;       // 0..15 (col group)
    const int blockRow = blockIdx.x * BM;
    const int blockCol = blockIdx.y * BN;
    const int K = K1 + K2;
    const int M = NN;

    float acc[4][4];
    #pragma unroll
    for (int m = 0; m < 4; m++)
        #pragma unroll
        for (int n = 0; n < 4; n++) acc[m][n] = 0.f;

    for (int k0 = 0; k0 < K; k0 += BK) {
        // load A tile (BM x BK): 4 elems/thread, k contiguous within 16 lanes
        #pragma unroll
        for (int i = 0; i < 4; i++) {
            int idx = t + i * 256;
            int m  = idx >> 4;
            int kk = idx & 15;
            int row = blockRow + m;
            int k = k0 + kk;
            float v = 0.f;
            if (row < M) {
                if (k < K1) {
                    v = A1[(size_t)row * K1 + k];
                } else {
                    int k2 = k - K1;
                    v = A2[(size_t)row * K2 + k2];
                    if (Rbuf) v *= Rbuf[(size_t)row * 256 + 128 + k2];
                }
            }
            As[m][kk] = v;
        }
        // load B tile (BK x BN)
        #pragma unroll
        for (int i = 0; i < 4; i++) {
            int idx = t + i * 256;
            int kk = idx >> 6;
            int c  = idx & 63;
            Bs[kk][c] = B[(size_t)(k0 + kk) * ldb + colOff + blockCol + c];
        }
        __syncthreads();

        #pragma unroll
        for (int kk = 0; kk < BK; kk++) {
            float ra[4], rb[4];
            #pragma unroll
            for (int m = 0; m < 4; m++) ra[m] = As[ty * 4 + m][kk];
            #pragma unroll
            for (int n = 0; n < 4; n++) rb[n] = Bs[kk][tx * 4 + n];
            #pragma unroll
            for (int m = 0; m < 4; m++)
                #pragma unroll
                for (int n = 0; n < 4; n++)
                    acc[m][n] = fmaf(ra[m], rb[n], acc[m][n]);
        }
        __syncthreads();
    }

    // epilogue
    #pragma unroll
    for (int m = 0; m < 4; m++) {
        int row = blockRow + ty * 4 + m;
        if (row >= M) continue;
        #pragma unroll
        for (int n = 0; n < 4; n++) {
            int col = blockCol + tx * 4 + n;
            float v = acc[m][n] + bias[col];
            if (mode == 0) {
                out0[(size_t)row * NC + col] = 1.f / (1.f + expf(-v));
            } else if (mode == 1) {
                float ht = tanhf(v);
                float z  = Zbuf[(size_t)row * 256 + col];
                float hs = Hs[(size_t)row * 128 + col];
                float h  = z * hs + (1.f - z) * ht;
                out0[(size_t)row * 128 + col] = h;
                out1[(size_t)row * 128 + col] = fmaxf(h, 0.f);
            } else {
                out0[(size_t)row * 64 + col] = v;
            }
        }
    }
}

// ---------------- launch ------------------------------------------------------
extern "C" void kernel_launch(void* const* d_in, const int* in_sizes, int n_in,
                              void* d_out, int out_size) {
    const int*   ei  = (const int*)d_in[0];
    const float* X   = (const float*)d_in[1];
    const float* ew  = (const float*)d_in[2];
    const float* Hs  = (const float*)d_in[3];
    const float* Wz  = (const float*)d_in[4];
    const float* bz  = (const float*)d_in[5];
    const float* Wr  = (const float*)d_in[6];
    const float* br  = (const float*)d_in[7];
    const float* Wh  = (const float*)d_in[8];
    const float* bh  = (const float*)d_in[9];
    const float* Lz  = (const float*)d_in[10];
    const float* Lzb = (const float*)d_in[11];
    const float* Lr  = (const float*)d_in[12];
    const float* Lrb = (const float*)d_in[13];
    const float* Lh  = (const float*)d_in[14];
    const float* Lhb = (const float*)d_in[15];
    const float* LoW = (const float*)d_in[16];
    const float* LoB = (const float*)d_in[17];

    const int E = in_sizes[2];

    float* out   = (float*)d_out;
    float* out_y = out;                       // N x 64
    float* out_h = out + (size_t)NN * FF;     // N x 128

    void *pAX, *pZR, *pReluh, *pWcat, *pBcat;
    cudaGetSymbolAddress(&pAX, g_AX);
    cudaGetSymbolAddress(&pZR, g_ZR);
    cudaGetSymbolAddress(&pReluh, g_reluh);
    cudaGetSymbolAddress(&pWcat, g_Wcat);
    cudaGetSymbolAddress(&pBcat, g_bcat);

    // 1. pack weights
    k_pack<<<(192 * 384 + 384 + 255) / 256, 256>>>(Wz, bz, Wr, br, Wh, bh,
                                                   Lz, Lzb, Lr, Lrb, Lh, Lhb);
    // 2. degree + norm
    k_initdeg<<<(NN + 255) / 256, 256>>>();
    k_deg<<<(E + 255) / 256, 256>>>(ei, ew, E);
    k_dinv<<<(NN + 255) / 256, 256>>>();
    // 3. aggregate X once (GCN linearity)
    k_axinit<<<(NN * 16 + 255) / 256, 256>>>(X);
    k_agg<<<(E * 16 + 255) / 256, 256>>>(ei, ew, X, E);

    const int gridM = (NN + BM - 1) / BM;  // 782

    // 4. GEMM1: [AX | Hs] @ W1 -> sigmoid -> Z,R
    {
        dim3 grid(gridM, 256 / BN);
        gemm_kernel<<<grid, 256>>>((const float*)pAX, 64, Hs, 128, nullptr,
                                   (const float*)pWcat, 384, 0,
                                   (const float*)pBcat, 256, 0,
                                   nullptr, nullptr, (float*)pZR, nullptr);
    }
    // 5. GEMM2: [AX | Hs*R] @ W2 -> tanh -> GRU update -> h, relu(h)
    {
        dim3 grid(gridM, 128 / BN);
        gemm_kernel<<<grid, 256>>>((const float*)pAX, 64, Hs, 128, (const float*)pZR,
                                   (const float*)pWcat, 384, 256,
                                   (const float*)pBcat + 256, 128, 1,
                                   (const float*)pZR, Hs, out_h, (float*)pReluh);
    }
    // 6. GEMM3: relu(h) @ Lout + b -> y
    {
        dim3 grid(gridM, 64 / BN);
        gemm_kernel<<<grid, 256>>>((const float*)pReluh, 128, nullptr, 0, nullptr,
                                   LoW, 64, 0, LoB, 64, 2,
                                   nullptr, nullptr, out_y, nullptr);
    }
}

// round 2
// speedup vs baseline: 1.9692x; 1.9692x over previous
#include <cuda_runtime.h>
#include <cstdint>

// Problem constants
#define NN 50000
#define FF 64
#define HH 128

// ---------------- device scratch (static globals, no cudaMalloc) -------------
__device__ float g_deg[NN];
__device__ float g_dinv[NN];
__device__ float g_AX[(size_t)NN * FF];          // aggregated X  (N x 64)
__device__ float g_ZR[(size_t)NN * 256];         // Z in cols 0..127, R in 128..255
__device__ float g_reluh[(size_t)NN * HH];       // relu(h)
__device__ float g_Wcat[192 * 384];              // packed gate weights
__device__ float g_bcat[384];                    // packed gate biases

// ---------------- weight packing --------------------------------------------
__global__ void k_pack(const float* Wz, const float* bz,
                       const float* Wr, const float* br,
                       const float* Wh, const float* bh,
                       const float* Lz, const float* Lzb,
                       const float* Lr, const float* Lrb,
                       const float* Lh, const float* Lhb) {
    int idx = blockIdx.x * blockDim.x + threadIdx.x;
    const int total = 192 * 384;
    if (idx < total) {
        int k = idx / 384, j = idx % 384;
        int g = j >> 7;
        int jj = j & 127;
        const float* W = (g == 0) ? Wz : (g == 1) ? Wr : Wh;
        const float* L = (g == 0) ? Lz : (g == 1) ? Lr : Lh;
        float v;
        if (k < 64) {
            v = 0.f;
            #pragma unroll 8
            for (int t = 0; t < 128; t++) v += W[k * 128 + t] * L[t * 128 + jj];
        } else {
            v = L[(128 + (k - 64)) * 128 + jj];
        }
        g_Wcat[k * 384 + j] = v;
    } else if (idx < total + 384) {
        int j = idx - total;
        int g = j >> 7;
        int jj = j & 127;
        const float* bg = (g == 0) ? bz : (g == 1) ? br : bh;
        const float* L  = (g == 0) ? Lz : (g == 1) ? Lr : Lh;
        const float* Lb = (g == 0) ? Lzb : (g == 1) ? Lrb : Lhb;
        float v = Lb[jj];
        for (int t = 0; t < 128; t++) v += bg[t] * L[t * 128 + jj];
        g_bcat[j] = v;
    }
}

// ---------------- degree / normalization ------------------------------------
__global__ void k_initdeg() {
    int i = blockIdx.x * blockDim.x + threadIdx.x;
    if (i < NN) g_deg[i] = 1.0f;  // self-loop weight
}

__global__ void k_deg(const int* ei, const float* ew, int E) {
    int e = blockIdx.x * blockDim.x + threadIdx.x;
    if (e < E) atomicAdd(&g_deg[ei[E + e]], ew[e]);
}

__global__ void k_dinv() {
    int i = blockIdx.x * blockDim.x + threadIdx.x;
    if (i < NN) {
        float d = g_deg[i];
        g_dinv[i] = (d > 0.f) ? rsqrtf(d) : 0.f;
    }
}

// AX init = self-loop term: dinv[i]^2 * X[i,:]
__global__ void k_axinit(const float* __restrict__ X) {
    int tid = blockIdx.x * blockDim.x + threadIdx.x;
    if (tid >= NN * 16) return;
    int i = tid >> 4, q = tid & 15;
    float di = g_dinv[i];
    float s = di * di;
    float4 x = reinterpret_cast<const float4*>(X + (size_t)i * 64)[q];
    float4 v = make_float4(x.x * s, x.y * s, x.z * s, x.w * s);
    reinterpret_cast<float4*>(g_AX + (size_t)i * 64)[q] = v;
}

// Edge scatter: AX[dst] += dinv[src]*w*dinv[dst] * X[src]   (16 threads/edge)
__global__ void k_agg(const int* __restrict__ ei, const float* __restrict__ ew,
                      const float* __restrict__ X, int E) {
    int tid = blockIdx.x * blockDim.x + threadIdx.x;
    int e = tid >> 4;
    if (e >= E) return;
    int q = tid & 15;
    int s = ei[e];
    int d = ei[E + e];
    float norm = g_dinv[s] * ew[e] * g_dinv[d];
    float4 x = reinterpret_cast<const float4*>(X + (size_t)s * 64)[q];
    float* p = g_AX + (size_t)d * 64 + q * 4;
    asm volatile("red.global.add.v4.f32 [%0], {%1, %2, %3, %4};"
                 :: "l"(p), "f"(x.x * norm), "f"(x.y * norm),
                    "f"(x.z * norm), "f"(x.w * norm)
                 : "memory");
}

// ---------------- tf32 tensor-core GEMM --------------------------------------
// C[M x *] = [A1 (M x K1) | A2 (M x K2) (optionally * R)] @ B(+colOff) + bias
// mode 0: sigmoid -> out0 (stride 256)
// mode 1: tanh, GRU update -> out0 = h (stride 128), out1 = relu(h)
// mode 2: plain            -> out0 = y (stride 64)
#define BM 128
#define BN 64
#define BK 32
#define ASTR 36   // smem row stride (floats) for A: gid*36+tig mod 32 all-distinct
#define BSTR 72   // smem row stride (floats) for B: tig*72+gid mod 32 all-distinct

__device__ __forceinline__ uint32_t f2tf32(float x) {
    uint32_t r;
    asm("cvt.rna.tf32.f32 %0, %1;" : "=r"(r) : "f"(x));
    return r;
}

__device__ __forceinline__ void mma_tf32(float* c, const uint32_t* a, const uint32_t* b) {
    asm volatile(
        "mma.sync.aligned.m16n8k8.row.col.f32.tf32.tf32.f32 "
        "{%0,%1,%2,%3}, {%4,%5,%6,%7}, {%8,%9}, {%0,%1,%2,%3};"
        : "+f"(c[0]), "+f"(c[1]), "+f"(c[2]), "+f"(c[3])
        : "r"(a[0]), "r"(a[1]), "r"(a[2]), "r"(a[3]), "r"(b[0]), "r"(b[1]));
}

__global__ void __launch_bounds__(256)
gemm_tc(const float* __restrict__ A1, int K1,
        const float* __restrict__ A2, int K2,
        const float* __restrict__ Rbuf,   // if non-null, A2 *= R (g_ZR cols 128..255)
        const float* __restrict__ B, int ldb, int colOff,
        const float* __restrict__ bias,
        int mode,
        const float* __restrict__ Zbuf,   // mode 1: Z (g_ZR cols 0..127)
        const float* __restrict__ Hs,     // mode 1
        float* __restrict__ out0,
        float* __restrict__ out1) {
    __shared__ uint32_t As[BM * ASTR];
    __shared__ uint32_t Bs[BK * BSTR];

    const int t    = threadIdx.x;
    const int lane = t & 31;
    const int wid  = t >> 5;
    const int gid  = lane >> 2;   // 0..7
    const int tig  = lane & 3;    // 0..3
    const int warpRow = wid & 3;  // 0..3 -> 32-row band
    const int warpCol = wid >> 2; // 0..1 -> 32-col band
    const int blockRow = blockIdx.x * BM;
    const int blockCol = blockIdx.y * BN;
    const int K = K1 + K2;

    float acc[2][4][4];
    #pragma unroll
    for (int mi = 0; mi < 2; mi++)
        #pragma unroll
        for (int ni = 0; ni < 4; ni++)
            #pragma unroll
            for (int c = 0; c < 4; c++) acc[mi][ni][c] = 0.f;

    for (int k0 = 0; k0 < K; k0 += BK) {
        const float* src;
        int stride, off;
        bool useR = false;
        if (k0 < K1) { src = A1; stride = K1; off = k0; }
        else { src = A2; stride = K2; off = k0 - K1; useR = (Rbuf != nullptr); }

        // load A tile (128 x 32): 4 float4 per thread
        #pragma unroll
        for (int i = 0; i < 4; i++) {
            int idx = t + i * 256;
            int row = idx >> 3;    // 0..127
            int q   = idx & 7;     // float4 index within 32-wide row
            int grow = blockRow + row;
            float4 v;
            if (grow < NN) {
                v = *(const float4*)(src + (size_t)grow * stride + off + q * 4);
                if (useR) {
                    float4 r = *(const float4*)(Rbuf + (size_t)grow * 256 + 128 + off + q * 4);
                    v.x *= r.x; v.y *= r.y; v.z *= r.z; v.w *= r.w;
                }
            } else {
                v = make_float4(0.f, 0.f, 0.f, 0.f);
            }
            uint4 tv = make_uint4(f2tf32(v.x), f2tf32(v.y), f2tf32(v.z), f2tf32(v.w));
            *(uint4*)(&As[row * ASTR + q * 4]) = tv;
        }
        // load B tile (32 x 64): 2 float4 per thread
        #pragma unroll
        for (int i = 0; i < 2; i++) {
            int idx = t + i * 256;
            int row = idx >> 4;    // 0..31
            int q   = idx & 15;    // float4 index within 64-wide row
            float4 v = *(const float4*)(B + (size_t)(k0 + row) * ldb + colOff + blockCol + q * 4);
            uint4 tv = make_uint4(f2tf32(v.x), f2tf32(v.y), f2tf32(v.z), f2tf32(v.w));
            *(uint4*)(&Bs[row * BSTR + q * 4]) = tv;
        }
        __syncthreads();

        #pragma unroll
        for (int ks = 0; ks < 4; ks++) {
            int kk = ks * 8;
            uint32_t af[2][4];
            #pragma unroll
            for (int mi = 0; mi < 2; mi++) {
                int mb = warpRow * 32 + mi * 16;
                af[mi][0] = As[(mb + gid) * ASTR + kk + tig];
                af[mi][1] = As[(mb + gid + 8) * ASTR + kk + tig];
                af[mi][2] = As[(mb + gid) * ASTR + kk + tig + 4];
                af[mi][3] = As[(mb + gid + 8) * ASTR + kk + tig + 4];
            }
            #pragma unroll
            for (int ni = 0; ni < 4; ni++) {
                int nb = warpCol * 32 + ni * 8;
                uint32_t bf[2];
                bf[0] = Bs[(kk + tig) * BSTR + nb + gid];
                bf[1] = Bs[(kk + tig + 4) * BSTR + nb + gid];
                mma_tf32(acc[0][ni], af[0], bf);
                mma_tf32(acc[1][ni], af[1], bf);
            }
        }
        __syncthreads();
    }

    // epilogue
    #pragma unroll
    for (int mi = 0; mi < 2; mi++) {
        #pragma unroll
        for (int ni = 0; ni < 4; ni++) {
            #pragma unroll
            for (int c = 0; c < 4; c++) {
                int row = blockRow + warpRow * 32 + mi * 16 + gid + ((c >= 2) ? 8 : 0);
                int col = blockCol + warpCol * 32 + ni * 8 + tig * 2 + (c & 1);
                if (row >= NN) continue;
                float v = acc[mi][ni][c] + bias[col];
                if (mode == 0) {
                    out0[(size_t)row * 256 + col] = 1.f / (1.f + expf(-v));
                } else if (mode == 1) {
                    float ht = tanhf(v);
                    float z  = Zbuf[(size_t)row * 256 + col];
                    float hs = Hs[(size_t)row * 128 + col];
                    float h  = z * hs + (1.f - z) * ht;
                    out0[(size_t)row * 128 + col] = h;
                    out1[(size_t)row * 128 + col] = fmaxf(h, 0.f);
                } else {
                    out0[(size_t)row * 64 + col] = v;
                }
            }
        }
    }
}

// ---------------- launch ------------------------------------------------------
extern "C" void kernel_launch(void* const* d_in, const int* in_sizes, int n_in,
                              void* d_out, int out_size) {
    const int*   ei  = (const int*)d_in[0];
    const float* X   = (const float*)d_in[1];
    const float* ew  = (const float*)d_in[2];
    const float* Hs  = (const float*)d_in[3];
    const float* Wz  = (const float*)d_in[4];
    const float* bz  = (const float*)d_in[5];
    const float* Wr  = (const float*)d_in[6];
    const float* br  = (const float*)d_in[7];
    const float* Wh  = (const float*)d_in[8];
    const float* bh  = (const float*)d_in[9];
    const float* Lz  = (const float*)d_in[10];
    const float* Lzb = (const float*)d_in[11];
    const float* Lr  = (const float*)d_in[12];
    const float* Lrb = (const float*)d_in[13];
    const float* Lh  = (const float*)d_in[14];
    const float* Lhb = (const float*)d_in[15];
    const float* LoW = (const float*)d_in[16];
    const float* LoB = (const float*)d_in[17];

    const int E = in_sizes[2];

    float* out   = (float*)d_out;
    float* out_y = out;                       // N x 64
    float* out_h = out + (size_t)NN * FF;     // N x 128

    void *pAX, *pZR, *pReluh, *pWcat, *pBcat;
    cudaGetSymbolAddress(&pAX, g_AX);
    cudaGetSymbolAddress(&pZR, g_ZR);
    cudaGetSymbolAddress(&pReluh, g_reluh);
    cudaGetSymbolAddress(&pWcat, g_Wcat);
    cudaGetSymbolAddress(&pBcat, g_bcat);

    // 1. pack weights
    k_pack<<<(192 * 384 + 384 + 255) / 256, 256>>>(Wz, bz, Wr, br, Wh, bh,
                                                   Lz, Lzb, Lr, Lrb, Lh, Lhb);
    // 2. degree + norm
    k_initdeg<<<(NN + 255) / 256, 256>>>();
    k_deg<<<(E + 255) / 256, 256>>>(ei, ew, E);
    k_dinv<<<(NN + 255) / 256, 256>>>();
    // 3. aggregate X once (GCN linearity)
    k_axinit<<<(NN * 16 + 255) / 256, 256>>>(X);
    k_agg<<<(E * 16 + 255) / 256, 256>>>(ei, ew, X, E);

    const int gridM = (NN + BM - 1) / BM;  // 391

    // 4. GEMM1: [AX | Hs] @ W1 -> sigmoid -> Z,R
    {
        dim3 grid(gridM, 256 / BN);
        gemm_tc<<<grid, 256>>>((const float*)pAX, 64, Hs, 128, nullptr,
                               (const float*)pWcat, 384, 0,
                               (const float*)pBcat, 0,
                               nullptr, nullptr, (float*)pZR, nullptr);
    }
    // 5. GEMM2: [AX | Hs*R] @ W2 -> tanh -> GRU update -> h, relu(h)
    {
        dim3 grid(gridM, 128 / BN);
        gemm_tc<<<grid, 256>>>((const float*)pAX, 64, Hs, 128, (const float*)pZR,
                               (const float*)pWcat, 384, 256,
                               (const float*)pBcat + 256, 1,
                               (const float*)pZR, Hs, out_h, (float*)pReluh);
    }
    // 6. GEMM3: relu(h) @ Lout + b -> y
    {
        dim3 grid(gridM, 64 / BN);
        gemm_tc<<<grid, 256>>>((const float*)pReluh, 128, nullptr, 0, nullptr,
                               LoW, 64, 0, LoB, 2,
                               nullptr, nullptr, out_y, nullptr);
    }
}